// round 5
// baseline (speedup 1.0000x reference)
#include <cuda_runtime.h>

#define Wd   1024
#define Hd   1024
#define Bd   16
#define RPB  8
#define NBLK ((Bd * Hd) / RPB)   // 2048 blocks
#define TPB  256                  // 256 threads * 4 floats = 1024 = one row

__device__ float g_partial[NBLK];
__device__ unsigned int g_ticket;   // zero-initialized; self-resets each run

__device__ __forceinline__ float4 hmax4(float4 t, float l, float r) {
    float4 h;
    h.x = fmaxf(l,   fmaxf(t.x, t.y));
    h.y = fmaxf(t.x, fmaxf(t.y, t.z));
    h.z = fmaxf(t.y, fmaxf(t.z, t.w));
    h.w = fmaxf(t.z, fmaxf(t.w, r));
    return h;
}

__global__ __launch_bounds__(TPB)
void bce_fused_kernel(const float* __restrict__ pred,
                      const float* __restrict__ tgt,
                      float* __restrict__ out) {
    const int r0 = blockIdx.x * RPB;       // first global row for this block
    const int x4 = threadIdx.x * 4;        // column of this thread's float4
    const bool has_left  = (x4 > 0);
    const bool has_right = (x4 + 4 < Wd);
    const int y0 = r0 & (Hd - 1);          // row within image (RPB divides Hd)

    // Load one target row: returns horizontal 3-max per lane, outputs raw float4.
    auto load_row = [&](int r, float4& t4) -> float4 {
        const float* p = tgt + (size_t)r * Wd + x4;
        t4 = *reinterpret_cast<const float4*>(p);
        float l  = has_left  ? __ldg(p - 1) : 0.0f;
        float rr = has_right ? __ldg(p + 4) : 0.0f;
        return hmax4(t4, l, rr);
    };

    float4 tcur, tnext, tdump;
    float4 hm_m1, hm_0, hm_p1;

    if (y0 > 0) hm_m1 = load_row(r0 - 1, tdump);
    else        hm_m1 = make_float4(0.f, 0.f, 0.f, 0.f);
    hm_0 = load_row(r0, tcur);

    float acc = 0.0f;

    #pragma unroll
    for (int i = 0; i < RPB; ++i) {
        const int r = r0 + i;
        const int y = y0 + i;

        if (y < Hd - 1) {
            hm_p1 = load_row(r + 1, tnext);
        } else {
            hm_p1 = make_float4(0.f, 0.f, 0.f, 0.f);
            tnext = make_float4(0.f, 0.f, 0.f, 0.f);
        }

        float4 p4 = *reinterpret_cast<const float4*>(pred + (size_t)r * Wd + x4);

        float dil[4];
        dil[0] = fmaxf(hm_m1.x, fmaxf(hm_0.x, hm_p1.x));
        dil[1] = fmaxf(hm_m1.y, fmaxf(hm_0.y, hm_p1.y));
        dil[2] = fmaxf(hm_m1.z, fmaxf(hm_0.z, hm_p1.z));
        dil[3] = fmaxf(hm_m1.w, fmaxf(hm_0.w, hm_p1.w));

        float tv[4] = {tcur.x, tcur.y, tcur.z, tcur.w};
        float xv[4] = {p4.x,   p4.y,   p4.z,   p4.w};

        #pragma unroll
        for (int j = 0; j < 4; ++j) {
            float t = tv[j];
            float x = xv[j];
            float w = (t > 0.5f) ? 20.0f : ((dil[j] > 0.5f) ? 5.0f : 1.0f);
            float a  = fabsf(x);
            float sp = __logf(1.0f + __expf(-a));     // log1p(exp(-|x|)), |x|>=0
            acc = fmaf(w, fmaxf(x, 0.0f) - x * t + sp, acc);
        }

        // roll the row window
        hm_m1 = hm_0;
        hm_0  = hm_p1;
        tcur  = tnext;
    }

    // ---- deterministic block reduction (fixed tree order) ----
    #pragma unroll
    for (int off = 16; off > 0; off >>= 1)
        acc += __shfl_down_sync(0xffffffffu, acc, off);

    __shared__ float smem[TPB / 32];
    __shared__ bool  is_last;
    const int lane = threadIdx.x & 31;
    const int wid  = threadIdx.x >> 5;
    if (lane == 0) smem[wid] = acc;
    __syncthreads();
    if (threadIdx.x == 0) {
        acc = smem[0];
        #pragma unroll
        for (int k = 1; k < TPB / 32; ++k) acc += smem[k];
        g_partial[blockIdx.x] = acc;
        __threadfence();                      // release partial before ticket
        unsigned t = atomicAdd(&g_ticket, 1u);
        is_last = (t == NBLK - 1u);
    }
    __syncthreads();

    // ---- last block performs the grid-wide final reduce (deterministic) ----
    if (is_last) {
        __threadfence();                      // acquire: see all partials
        double s = 0.0;
        #pragma unroll
        for (int k = 0; k < NBLK / TPB; ++k)
            s += (double)g_partial[threadIdx.x + k * TPB];

        #pragma unroll
        for (int off = 16; off > 0; off >>= 1)
            s += __shfl_down_sync(0xffffffffu, s, off);

        __shared__ double sm[TPB / 32];
        if (lane == 0) sm[wid] = s;
        __syncthreads();
        if (threadIdx.x == 0) {
            s = sm[0];
            #pragma unroll
            for (int k = 1; k < TPB / 32; ++k) s += sm[k];
            out[0] = (float)(s / (double)((size_t)Bd * Hd * Wd));
            g_ticket = 0u;                    // self-reset for next graph replay
        }
    }
}

extern "C" void kernel_launch(void* const* d_in, const int* in_sizes, int n_in,
                              void* d_out, int out_size) {
    const float* pred = (const float*)d_in[0];
    const float* tgt  = (const float*)d_in[1];
    float* out = (float*)d_out;

    bce_fused_kernel<<<NBLK, TPB>>>(pred, tgt, out);
}

// round 6
// speedup vs baseline: 1.1040x; 1.1040x over previous
#include <cuda_runtime.h>

#define Wd   1024
#define Hd   1024
#define Bd   16
#define RPB  8
#define NBLK ((Bd * Hd) / RPB)   // 2048 blocks
#define TPB  256                  // 256 threads * 4 floats = 1024 = one row

__device__ float g_partial[NBLK];
__device__ unsigned int g_ticket;   // zero-initialized; self-resets each run

__device__ __forceinline__ float4 hmax4(float4 t, float l, float r) {
    float4 h;
    h.x = fmaxf(l,   fmaxf(t.x, t.y));
    h.y = fmaxf(t.x, fmaxf(t.y, t.z));
    h.z = fmaxf(t.y, fmaxf(t.z, t.w));
    h.w = fmaxf(t.z, fmaxf(t.w, r));
    return h;
}

__global__ __launch_bounds__(TPB)
void bce_fused_kernel(const float* __restrict__ pred,
                      const float* __restrict__ tgt,
                      float* __restrict__ out) {
    const int r0   = blockIdx.x * RPB;     // first global row for this block
    const int x4   = threadIdx.x * 4;      // column of this thread's float4
    const int lane = threadIdx.x & 31;
    const int wid  = threadIdx.x >> 5;
    const bool edge_l = (lane == 0);
    const bool edge_r = (lane == 31);
    const bool has_left  = (x4 > 0);
    const bool has_right = (x4 + 4 < Wd);
    const int y0 = r0 & (Hd - 1);          // row within image (RPB divides Hd)

    // Load one target row; horizontal neighbors come from adjacent lanes via
    // shfl (memory only at warp-boundary lanes). Returns horizontal 3-max.
    auto load_row = [&](int r, float4& t4) -> float4 {
        const float* p = tgt + (size_t)r * Wd + x4;
        t4 = *reinterpret_cast<const float4*>(p);
        float l  = __shfl_up_sync(0xffffffffu, t4.w, 1);
        float rr = __shfl_down_sync(0xffffffffu, t4.x, 1);
        if (edge_l) l  = has_left  ? __ldg(p - 1) : 0.0f;
        if (edge_r) rr = has_right ? __ldg(p + 4) : 0.0f;
        return hmax4(t4, l, rr);
    };

    float4 tcur, tnext, tdump;
    float4 hm_m1, hm_0, hm_p1;

    if (y0 > 0) hm_m1 = load_row(r0 - 1, tdump);
    else        hm_m1 = make_float4(0.f, 0.f, 0.f, 0.f);
    hm_0 = load_row(r0, tcur);

    float acc = 0.0f;

    #pragma unroll
    for (int i = 0; i < RPB; ++i) {
        const int r = r0 + i;
        const int y = y0 + i;

        if (y < Hd - 1) {
            hm_p1 = load_row(r + 1, tnext);
        } else {
            hm_p1 = make_float4(0.f, 0.f, 0.f, 0.f);
            tnext = make_float4(0.f, 0.f, 0.f, 0.f);
        }

        float4 p4 = *reinterpret_cast<const float4*>(pred + (size_t)r * Wd + x4);

        float dil[4];
        dil[0] = fmaxf(hm_m1.x, fmaxf(hm_0.x, hm_p1.x));
        dil[1] = fmaxf(hm_m1.y, fmaxf(hm_0.y, hm_p1.y));
        dil[2] = fmaxf(hm_m1.z, fmaxf(hm_0.z, hm_p1.z));
        dil[3] = fmaxf(hm_m1.w, fmaxf(hm_0.w, hm_p1.w));

        float tv[4] = {tcur.x, tcur.y, tcur.z, tcur.w};
        float xv[4] = {p4.x,   p4.y,   p4.z,   p4.w};

        #pragma unroll
        for (int j = 0; j < 4; ++j) {
            float t = tv[j];
            float x = xv[j];
            float w = (t > 0.5f) ? 20.0f : ((dil[j] > 0.5f) ? 5.0f : 1.0f);
            float a  = fabsf(x);
            float sp = __logf(1.0f + __expf(-a));     // log1p(exp(-|x|)), |x|>=0
            acc = fmaf(w, fmaxf(x, 0.0f) - x * t + sp, acc);
        }

        // roll the row window
        hm_m1 = hm_0;
        hm_0  = hm_p1;
        tcur  = tnext;
    }

    // ---- deterministic block reduction (fixed tree order) ----
    #pragma unroll
    for (int off = 16; off > 0; off >>= 1)
        acc += __shfl_down_sync(0xffffffffu, acc, off);

    __shared__ float smem[TPB / 32];
    __shared__ bool  is_last;
    if (lane == 0) smem[wid] = acc;
    __syncthreads();
    if (threadIdx.x == 0) {
        acc = smem[0];
        #pragma unroll
        for (int k = 1; k < TPB / 32; ++k) acc += smem[k];
        g_partial[blockIdx.x] = acc;
        // acq_rel atomic: release orders the partial store before the ticket,
        // acquire makes all earlier releases visible. NO fence instruction,
        // so ptxas emits no CCTL.IVALL (no L1D flush for co-resident blocks).
        unsigned t;
        asm volatile("atom.add.acq_rel.gpu.global.u32 %0, [%1], %2;"
                     : "=r"(t)
                     : "l"(&g_ticket), "r"(1u)
                     : "memory");
        is_last = (t == NBLK - 1u);
    }
    __syncthreads();

    // ---- last block performs the grid-wide final reduce (deterministic) ----
    if (is_last) {
        double s = 0.0;
        #pragma unroll
        for (int k = 0; k < NBLK / TPB; ++k)
            s += (double)__ldcg(&g_partial[threadIdx.x + k * TPB]);  // L2-direct

        #pragma unroll
        for (int off = 16; off > 0; off >>= 1)
            s += __shfl_down_sync(0xffffffffu, s, off);

        __shared__ double sm[TPB / 32];
        if (lane == 0) sm[wid] = s;
        __syncthreads();
        if (threadIdx.x == 0) {
            s = sm[0];
            #pragma unroll
            for (int k = 1; k < TPB / 32; ++k) s += sm[k];
            out[0] = (float)(s / (double)((size_t)Bd * Hd * Wd));
            g_ticket = 0u;                    // self-reset for next graph replay
        }
    }
}

extern "C" void kernel_launch(void* const* d_in, const int* in_sizes, int n_in,
                              void* d_out, int out_size) {
    const float* pred = (const float*)d_in[0];
    const float* tgt  = (const float*)d_in[1];
    float* out = (float*)d_out;

    bce_fused_kernel<<<NBLK, TPB>>>(pred, tgt, out);
}

// round 7
// speedup vs baseline: 1.2968x; 1.1746x over previous
#include <cuda_runtime.h>

#define Wd   1024
#define Hd   1024
#define Bd   16
#define RPB  8
#define NBLK ((Bd * Hd) / RPB)   // 2048 blocks
#define TPB  256                  // 256 threads * 4 floats = 1024 = one row

// 1 / (16 * 1024 * 1024) = 2^-24, exact power of two -> exact scaling
#define INV_N 5.9604644775390625e-8f

__global__ void bce_zero_kernel(float* __restrict__ out) {
    if (threadIdx.x == 0) out[0] = 0.0f;
}

__device__ __forceinline__ float4 hmax4(float4 t, float l, float r) {
    float4 h;
    h.x = fmaxf(l,   fmaxf(t.x, t.y));
    h.y = fmaxf(t.x, fmaxf(t.y, t.z));
    h.z = fmaxf(t.y, fmaxf(t.z, t.w));
    h.w = fmaxf(t.z, fmaxf(t.w, r));
    return h;
}

__global__ __launch_bounds__(TPB)
void bce_main_kernel(const float* __restrict__ pred,
                     const float* __restrict__ tgt,
                     float* __restrict__ out) {
    const int r0 = blockIdx.x * RPB;       // first global row for this block
    const int x4 = threadIdx.x * 4;        // column of this thread's float4
    const bool has_left  = (x4 > 0);
    const bool has_right = (x4 + 4 < Wd);
    const int y0 = r0 & (Hd - 1);          // row within image (RPB divides Hd)

    // Load one target row: raw float4 out-param, returns horizontal 3-max.
    auto load_row = [&](int r, float4& t4) -> float4 {
        const float* p = tgt + (size_t)r * Wd + x4;
        t4 = *reinterpret_cast<const float4*>(p);
        float l  = has_left  ? __ldg(p - 1) : 0.0f;
        float rr = has_right ? __ldg(p + 4) : 0.0f;
        return hmax4(t4, l, rr);
    };

    float4 tcur, tnext, tdump;
    float4 hm_m1, hm_0, hm_p1;

    if (y0 > 0) hm_m1 = load_row(r0 - 1, tdump);
    else        hm_m1 = make_float4(0.f, 0.f, 0.f, 0.f);
    hm_0 = load_row(r0, tcur);

    float acc = 0.0f;

    #pragma unroll
    for (int i = 0; i < RPB; ++i) {
        const int r = r0 + i;
        const int y = y0 + i;

        if (y < Hd - 1) {
            hm_p1 = load_row(r + 1, tnext);
        } else {
            hm_p1 = make_float4(0.f, 0.f, 0.f, 0.f);
            tnext = make_float4(0.f, 0.f, 0.f, 0.f);
        }

        float4 p4 = *reinterpret_cast<const float4*>(pred + (size_t)r * Wd + x4);

        float dil[4];
        dil[0] = fmaxf(hm_m1.x, fmaxf(hm_0.x, hm_p1.x));
        dil[1] = fmaxf(hm_m1.y, fmaxf(hm_0.y, hm_p1.y));
        dil[2] = fmaxf(hm_m1.z, fmaxf(hm_0.z, hm_p1.z));
        dil[3] = fmaxf(hm_m1.w, fmaxf(hm_0.w, hm_p1.w));

        float tv[4] = {tcur.x, tcur.y, tcur.z, tcur.w};
        float xv[4] = {p4.x,   p4.y,   p4.z,   p4.w};

        #pragma unroll
        for (int j = 0; j < 4; ++j) {
            float t = tv[j];
            float x = xv[j];
            float w = (t > 0.5f) ? 20.0f : ((dil[j] > 0.5f) ? 5.0f : 1.0f);
            float a  = fabsf(x);
            float sp = __logf(1.0f + __expf(-a));     // log1p(exp(-|x|)), |x|>=0
            acc = fmaf(w, fmaxf(x, 0.0f) - x * t + sp, acc);
        }

        // roll the row window
        hm_m1 = hm_0;
        hm_0  = hm_p1;
        tcur  = tnext;
    }

    // ---- block reduction (fixed tree order), then one relaxed atomic ----
    #pragma unroll
    for (int off = 16; off > 0; off >>= 1)
        acc += __shfl_down_sync(0xffffffffu, acc, off);

    __shared__ float smem[TPB / 32];
    const int lane = threadIdx.x & 31;
    const int wid  = threadIdx.x >> 5;
    if (lane == 0) smem[wid] = acc;
    __syncthreads();
    if (threadIdx.x == 0) {
        acc = smem[0];
        #pragma unroll
        for (int k = 1; k < TPB / 32; ++k) acc += smem[k];
        // exact 2^-24 scale; relaxed fp32 atomic (REDG) — no fence, no acquire
        atomicAdd(out, acc * INV_N);
    }
}

extern "C" void kernel_launch(void* const* d_in, const int* in_sizes, int n_in,
                              void* d_out, int out_size) {
    const float* pred = (const float*)d_in[0];
    const float* tgt  = (const float*)d_in[1];
    float* out = (float*)d_out;

    bce_zero_kernel<<<1, 32>>>(out);
    bce_main_kernel<<<NBLK, TPB>>>(pred, tgt, out);
}